// round 7
// baseline (speedup 1.0000x reference)
#include <cuda_runtime.h>
#include <stdint.h>

// Shapes (fixed):
//   x:        (B, M, N)  float32          B=32, M=512, N=128
//   location: (B, M, 2)  int64/int32 (y, x), H=W=128
//   out:      (B, N, H, W) float32
#define BB   32
#define MM   512
#define NN   128
#define WPX  128
#define HWPX 16384   // 128*128
#define HW4  4096    // HWPX/4
#define PPB  1024    // pixels per block (256 threads x 4)

// ---------------------------------------------------------------------------
// Single fused kernel. Block = (pixel range of 1024, batch b); each block
// produces ALL 128 channels for its pixel range, so the smem inverse map is
// built ONCE per (b, range) instead of once per channel-chunk (8x less
// Phase-A work than R6).
//
// Phase A: build 2 KB smem inverse map by scanning batch b's 512 locations
//          (2 per thread, L2-resident). int64-vs-int32 layout detected via
//          __syncthreads_and on odd int32 words (all-zero <=> int64; under
//          int32 these are x coords ~U[0,128), P(all 256 zero) ~ 2^-1792).
// Phase B: per 16-channel chunk: 16 predicated LDG.128 hoisted (MLP=16),
//          register transpose, 16 fully coalesced STG.128 (warp = 512B
//          bursts). 8 chunks cover all 128 channels.
__global__ void __launch_bounds__(256) fused_scatter_kernel(
        const float4* __restrict__ xin,
        const int*    __restrict__ loc32,
        float4*       __restrict__ out) {
    __shared__ short s_inv[PPB];

    const int t  = threadIdx.x;
    const int b  = blockIdx.y;
    const int p0 = blockIdx.x * PPB;          // first pixel of this block

    // --- Phase A: smem inverse map ----------------------------------------
    ((int*)s_inv)[2 * t]     = -1;            // 4 shorts = -1 per thread
    ((int*)s_inv)[2 * t + 1] = -1;

    const int* locb32 = loc32 + b * MM * 2;   // int32 view of batch b
    const int* locb64 = loc32 + b * MM * 4;   // int64 view (int32 pairs)

    // layout probe (doubles as the barrier ordering smem init vs scatter):
    int is64 = __syncthreads_and(loc32[2 * t + 1] == 0);

    #pragma unroll
    for (int k = 0; k < 2; k++) {
        int e = t + 256 * k;                  // entity m in [0, 512)
        int y, x;
        if (is64) { y = locb64[4 * e]; x = locb64[4 * e + 2]; }
        else      { y = locb32[2 * e]; x = locb32[2 * e + 1]; }
        int rel = y * WPX + x - p0;
        if ((unsigned)rel < PPB) s_inv[rel] = (short)e;
    }
    __syncthreads();

    // --- Phase B: gather + zero-fill, all 128 channels --------------------
    short4 iv = ((const short4*)s_inv)[t];
    int m0 = iv.x, m1 = iv.y, m2 = iv.z, m3 = iv.w;
    bool v0 = m0 >= 0, v1 = m1 >= 0, v2 = m2 >= 0, v3 = m3 >= 0;
    int i0 = m0 * (NN / 4), i1 = m1 * (NN / 4);
    int i2 = m2 * (NN / 4), i3 = m3 * (NN / 4);

    const float4* xb = xin + b * (MM * NN / 4);
    float4*       o  = out + b * NN * HW4 + (p0 >> 2) + t;
    const float4  z  = make_float4(0.f, 0.f, 0.f, 0.f);

    #pragma unroll
    for (int c = 0; c < NN / 16; c++) {       // 8 chunks of 16 channels
        const float4* xc = xb + c * 4;        // channels c*16 .. c*16+15

        float4 e0[4], e1[4], e2[4], e3[4];
        #pragma unroll
        for (int q = 0; q < 4; q++) {
            e0[q] = v0 ? __ldg(xc + i0 + q) : z;
            e1[q] = v1 ? __ldg(xc + i1 + q) : z;
            e2[q] = v2 ? __ldg(xc + i2 + q) : z;
            e3[q] = v3 ? __ldg(xc + i3 + q) : z;
        }

        float4* oc = o + (c * 16) * HW4;
        #pragma unroll
        for (int q = 0; q < 4; q++) {
            float4 a = e0[q], d = e1[q], g = e2[q], f = e3[q];
            oc[(4 * q + 0) * HW4] = make_float4(a.x, d.x, g.x, f.x);
            oc[(4 * q + 1) * HW4] = make_float4(a.y, d.y, g.y, f.y);
            oc[(4 * q + 2) * HW4] = make_float4(a.z, d.z, g.z, f.z);
            oc[(4 * q + 3) * HW4] = make_float4(a.w, d.w, g.w, f.w);
        }
    }
}

// ---------------------------------------------------------------------------
extern "C" void kernel_launch(void* const* d_in, const int* in_sizes, int n_in,
                              void* d_out, int out_size) {
    const float* x     = (const float*)d_in[0];
    const int*   loc32 = (const int*)d_in[1];
    float*       out   = (float*)d_out;
    (void)in_sizes; (void)n_in; (void)out_size;

    // One launch: (16 pixel-ranges, 32 batches) x 256 threads.
    fused_scatter_kernel<<<dim3(HWPX / PPB, BB), 256>>>(
        (const float4*)x, loc32, (float4*)out);
}

// round 8
// speedup vs baseline: 1.2006x; 1.2006x over previous
#include <cuda_runtime.h>
#include <stdint.h>

// Shapes (fixed):
//   x:        (B, M, N)  float32          B=32, M=512, N=128
//   location: (B, M, 2)  int64/int32 (y, x), H=W=128
//   out:      (B, N, H, W) float32
#define BB   32
#define MM   512
#define NN   128
#define WPX  128
#define HWPX 16384   // 128*128
#define HW4  4096    // HWPX/4
#define PPB  1024    // pixels per block (256 threads x 4)
#define CPB  32      // channels per block (2 chunks of 16)

// ---------------------------------------------------------------------------
// Single fused kernel. Block = (pixel range of 1024, 32-channel group, b).
// Grid = 16 x 4 x 32 = 2048 blocks: large enough to fill the chip (>=2.7
// waves at the 5-block/SM occupancy cap -- R7 showed grid 512 starves it),
// while Phase-A replication is 4x instead of R6's 8x.
//
// Phase A: build 2 KB smem inverse map for this pixel range by scanning
//          batch b's 512 locations (2 per thread, L2-resident).
//          int64-vs-int32 layout detected via __syncthreads_and on odd int32
//          words (all-zero <=> int64; under int32 these are x coords
//          ~U[0,128), P(all 256 zero) ~ 2^-1792).
// Phase B: per 16-channel chunk: 16 predicated LDG.128 hoisted (MLP=16),
//          register transpose, 16 fully coalesced STG.128 (warp = 512B
//          bursts). 2 chunks cover this block's 32 channels.
__global__ void __launch_bounds__(256) fused_scatter_kernel(
        const float4* __restrict__ xin,
        const int*    __restrict__ loc32,
        float4*       __restrict__ out) {
    __shared__ short s_inv[PPB];

    const int t  = threadIdx.x;
    const int b  = blockIdx.z;
    const int c0 = blockIdx.y * (CPB / 4);    // first float4-channel index
    const int p0 = blockIdx.x * PPB;          // first pixel of this block

    // --- Phase A: smem inverse map ----------------------------------------
    ((int*)s_inv)[2 * t]     = -1;            // 4 shorts = -1 per thread
    ((int*)s_inv)[2 * t + 1] = -1;

    const int* locb32 = loc32 + b * MM * 2;   // int32 view of batch b
    const int* locb64 = loc32 + b * MM * 4;   // int64 view (int32 pairs)

    // layout probe (doubles as the barrier ordering smem init vs scatter):
    int is64 = __syncthreads_and(loc32[2 * t + 1] == 0);

    #pragma unroll
    for (int k = 0; k < 2; k++) {
        int e = t + 256 * k;                  // entity m in [0, 512)
        int y, x;
        if (is64) { y = locb64[4 * e]; x = locb64[4 * e + 2]; }
        else      { y = locb32[2 * e]; x = locb32[2 * e + 1]; }
        int rel = y * WPX + x - p0;
        if ((unsigned)rel < PPB) s_inv[rel] = (short)e;
    }
    __syncthreads();

    // --- Phase B: gather + zero-fill, 32 channels -------------------------
    short4 iv = ((const short4*)s_inv)[t];
    int m0 = iv.x, m1 = iv.y, m2 = iv.z, m3 = iv.w;
    bool v0 = m0 >= 0, v1 = m1 >= 0, v2 = m2 >= 0, v3 = m3 >= 0;
    int i0 = m0 * (NN / 4), i1 = m1 * (NN / 4);
    int i2 = m2 * (NN / 4), i3 = m3 * (NN / 4);

    const float4* xb = xin + b * (MM * NN / 4) + c0;
    float4*       o  = out + (b * NN + 4 * c0) * HW4 + (p0 >> 2) + t;
    const float4  z  = make_float4(0.f, 0.f, 0.f, 0.f);

    #pragma unroll
    for (int c = 0; c < CPB / 16; c++) {      // 2 chunks of 16 channels
        const float4* xc = xb + c * 4;

        float4 e0[4], e1[4], e2[4], e3[4];
        #pragma unroll
        for (int q = 0; q < 4; q++) {
            e0[q] = v0 ? __ldg(xc + i0 + q) : z;
            e1[q] = v1 ? __ldg(xc + i1 + q) : z;
            e2[q] = v2 ? __ldg(xc + i2 + q) : z;
            e3[q] = v3 ? __ldg(xc + i3 + q) : z;
        }

        float4* oc = o + (c * 16) * HW4;
        #pragma unroll
        for (int q = 0; q < 4; q++) {
            float4 a = e0[q], d = e1[q], g = e2[q], f = e3[q];
            oc[(4 * q + 0) * HW4] = make_float4(a.x, d.x, g.x, f.x);
            oc[(4 * q + 1) * HW4] = make_float4(a.y, d.y, g.y, f.y);
            oc[(4 * q + 2) * HW4] = make_float4(a.z, d.z, g.z, f.z);
            oc[(4 * q + 3) * HW4] = make_float4(a.w, d.w, g.w, f.w);
        }
    }
}

// ---------------------------------------------------------------------------
extern "C" void kernel_launch(void* const* d_in, const int* in_sizes, int n_in,
                              void* d_out, int out_size) {
    const float* x     = (const float*)d_in[0];
    const int*   loc32 = (const int*)d_in[1];
    float*       out   = (float*)d_out;
    (void)in_sizes; (void)n_in; (void)out_size;

    // One launch: (16 pixel-ranges, 4 channel-groups, 32 batches) x 256 thr.
    fused_scatter_kernel<<<dim3(HWPX / PPB, NN / CPB, BB), 256>>>(
        (const float4*)x, loc32, (float4*)out);
}